// round 5
// baseline (speedup 1.0000x reference)
#include <cuda_runtime.h>
#include <math.h>
#include <stdint.h>

#define B_ 16
#define N_ 1024
#define C_ 256

#define KC   16            // k-chunk
#define STR  20            // smem row stride (floats)
#define TILE (128 * STR)   // floats per tile

// ---------------------------------------------------------------------------
// mma.sync m16n8k8 tf32, row.col, fp32 accumulate
// ---------------------------------------------------------------------------
__device__ __forceinline__ void mma_tf32(float* d,
                                         uint32_t a0, uint32_t a1,
                                         uint32_t a2, uint32_t a3,
                                         uint32_t b0, uint32_t b1) {
    asm volatile(
        "mma.sync.aligned.m16n8k8.row.col.f32.tf32.tf32.f32 "
        "{%0,%1,%2,%3}, {%4,%5,%6,%7}, {%8,%9}, {%0,%1,%2,%3};"
        : "+f"(d[0]), "+f"(d[1]), "+f"(d[2]), "+f"(d[3])
        : "r"(a0), "r"(a1), "r"(a2), "r"(a3), "r"(b0), "r"(b1));
}

__device__ __forceinline__ void split_tf32(float x, float& h, float& l) {
    h = __uint_as_float(__float_as_uint(x) & 0xFFFFE000u);
    l = x - h;
}

__device__ __forceinline__ uint32_t f2u(float x) { return __float_as_uint(x); }

// ---------------------------------------------------------------------------
// Shared compute: one k-chunk (KC=16) of 128x128 tile on 8 warps (2x4).
// Layout: fragment pairs (k, k+4) adjacent via column permutation.
// ---------------------------------------------------------------------------
__device__ __forceinline__ void compute_chunk(
    const float* __restrict__ Ah, const float* __restrict__ Al,
    const float* __restrict__ Bh, const float* __restrict__ Bl,
    float acc[4][4][4], int wm, int wn, int g, int cq)
{
#pragma unroll
    for (int s = 0; s < KC; s += 8) {
        int co = s + 2 * cq;                 // permuted col offset of (cq, cq+4)
        float2 ah0[4], ah1[4], al0[4], al1[4];
#pragma unroll
        for (int i = 0; i < 4; i++) {
            int r0 = (wm * 64 + i * 16 + g) * STR + co;
            int r1 = r0 + 8 * STR;
            ah0[i] = *reinterpret_cast<const float2*>(&Ah[r0]);  // {a0,a2}
            ah1[i] = *reinterpret_cast<const float2*>(&Ah[r1]);  // {a1,a3}
            al0[i] = *reinterpret_cast<const float2*>(&Al[r0]);
            al1[i] = *reinterpret_cast<const float2*>(&Al[r1]);
        }
#pragma unroll
        for (int j = 0; j < 4; j++) {
            int bi = (wn * 32 + j * 8 + g) * STR + co;
            float2 bh = *reinterpret_cast<const float2*>(&Bh[bi]);  // {b0,b1}
            float2 bl = *reinterpret_cast<const float2*>(&Bl[bi]);
            uint32_t bh0 = f2u(bh.x), bh1 = f2u(bh.y);
            uint32_t bl0 = f2u(bl.x), bl1 = f2u(bl.y);
#pragma unroll
            for (int i = 0; i < 4; i++) {
                mma_tf32(acc[i][j], f2u(ah0[i].x), f2u(ah1[i].x),
                                    f2u(ah0[i].y), f2u(ah1[i].y), bh0, bh1);
                mma_tf32(acc[i][j], f2u(al0[i].x), f2u(al1[i].x),
                                    f2u(al0[i].y), f2u(al1[i].y), bh0, bh1);
                mma_tf32(acc[i][j], f2u(ah0[i].x), f2u(ah1[i].x),
                                    f2u(ah0[i].y), f2u(ah1[i].y), bl0, bl1);
            }
        }
    }
}

// store one float4 (k = c4..c4+3) into permuted split tiles
__device__ __forceinline__ void store_split4(
    float* __restrict__ Th, float* __restrict__ Tl,
    int row, int c4, float4 v)
{
    int base = row * STR + ((c4 >> 3) << 3) + ((c4 >> 2) & 1);
    float h, l;
    split_tf32(v.x, h, l); Th[base + 0] = h; Tl[base + 0] = l;
    split_tf32(v.y, h, l); Th[base + 2] = h; Tl[base + 2] = l;
    split_tf32(v.z, h, l); Th[base + 4] = h; Tl[base + 4] = l;
    split_tf32(v.w, h, l); Th[base + 6] = h; Tl[base + 6] = l;
}

// ---------------------------------------------------------------------------
// Kernel 1: attn = masked((Q K^T + dis) * 0.0625). Double-buffered.
// ---------------------------------------------------------------------------
__global__ __launch_bounds__(256, 2) void qk_scores_kernel(
    const float* __restrict__ Q,
    const float* __restrict__ K,
    const float* __restrict__ dis,
    const int*   __restrict__ mask,
    float* __restrict__ attn)
{
    extern __shared__ float smem[];   // [2][4][TILE]: Ah Al Bh Bl per buffer

    const int b     = blockIdx.z;
    const int qBase = blockIdx.y * 128;
    const int kBase = blockIdx.x * 128;

    const float* Qb = Q + (size_t)b * N_ * C_;
    const float* Kb = K + (size_t)b * N_ * C_;

    const int tid  = threadIdx.x;
    const int lane = tid & 31;
    const int w    = tid >> 5;
    const int wm   = w >> 2;
    const int wn   = w & 3;
    const int g    = lane >> 2;
    const int cq   = lane & 3;

    const int lrow[2] = { (tid        ) >> 2, (tid + 256) >> 2 };
    const int lc4     = (tid & 3) * 4;

    float acc[4][4][4];
#pragma unroll
    for (int i = 0; i < 4; i++)
#pragma unroll
        for (int j = 0; j < 4; j++)
#pragma unroll
            for (int r = 0; r < 4; r++) acc[i][j][r] = 0.0f;

    float4 vq[2], vk[2];
    // prologue: load + store chunk 0 into buf 0
#pragma unroll
    for (int e = 0; e < 2; e++) {
        vq[e] = *reinterpret_cast<const float4*>(&Qb[(size_t)(qBase + lrow[e]) * C_ + lc4]);
        vk[e] = *reinterpret_cast<const float4*>(&Kb[(size_t)(kBase + lrow[e]) * C_ + lc4]);
    }
    {
        float* Ah = smem;            float* Al = smem + TILE;
        float* Bh = smem + 2 * TILE; float* Bl = smem + 3 * TILE;
#pragma unroll
        for (int e = 0; e < 2; e++) {
            store_split4(Ah, Al, lrow[e], lc4, vq[e]);
            store_split4(Bh, Bl, lrow[e], lc4, vk[e]);
        }
    }
    __syncthreads();

    int buf = 0;
    for (int c0 = 0; c0 < C_; c0 += KC, buf ^= 1) {
        const bool more = (c0 + KC) < C_;
        if (more) {
#pragma unroll
            for (int e = 0; e < 2; e++) {
                vq[e] = *reinterpret_cast<const float4*>(
                    &Qb[(size_t)(qBase + lrow[e]) * C_ + c0 + KC + lc4]);
                vk[e] = *reinterpret_cast<const float4*>(
                    &Kb[(size_t)(kBase + lrow[e]) * C_ + c0 + KC + lc4]);
            }
        }
        const float* base = smem + buf * 4 * TILE;
        compute_chunk(base, base + TILE, base + 2 * TILE, base + 3 * TILE,
                      acc, wm, wn, g, cq);
        if (more) {
            float* nb = smem + (buf ^ 1) * 4 * TILE;
#pragma unroll
            for (int e = 0; e < 2; e++) {
                store_split4(nb,            nb + TILE,     lrow[e], lc4, vq[e]);
                store_split4(nb + 2 * TILE, nb + 3 * TILE, lrow[e], lc4, vk[e]);
            }
        }
        __syncthreads();
    }

    // epilogue: add dis, scale, mask -> attn
#pragma unroll
    for (int i = 0; i < 4; i++) {
        int r0 = qBase + wm * 64 + i * 16 + g;
        int r1 = r0 + 8;
#pragma unroll
        for (int j = 0; j < 4; j++) {
            int col = kBase + wn * 32 + j * 8 + 2 * cq;
            size_t i0 = ((size_t)b * N_ + r0) * N_ + col;
            size_t i1 = ((size_t)b * N_ + r1) * N_ + col;
            float2 d0 = *reinterpret_cast<const float2*>(&dis[i0]);
            float2 d1 = *reinterpret_cast<const float2*>(&dis[i1]);
            int2   m0 = *reinterpret_cast<const int2*>(&mask[i0]);
            int2   m1 = *reinterpret_cast<const int2*>(&mask[i1]);
            float2 o0, o1;
            o0.x = m0.x ? -INFINITY : (acc[i][j][0] + d0.x) * 0.0625f;
            o0.y = m0.y ? -INFINITY : (acc[i][j][1] + d0.y) * 0.0625f;
            o1.x = m1.x ? -INFINITY : (acc[i][j][2] + d1.x) * 0.0625f;
            o1.y = m1.y ? -INFINITY : (acc[i][j][3] + d1.y) * 0.0625f;
            *reinterpret_cast<float2*>(&attn[i0]) = o0;
            *reinterpret_cast<float2*>(&attn[i1]) = o1;
        }
    }
}

// ---------------------------------------------------------------------------
// Kernel 2: row softmax, shuffle-based, float4 I/O. One block per row.
// ---------------------------------------------------------------------------
__global__ __launch_bounds__(256) void softmax_kernel(float* __restrict__ attn)
{
    __shared__ float s1[8], s2[8];
    const size_t base = (size_t)blockIdx.x * N_;
    const int t = threadIdx.x;
    const int w = t >> 5, lane = t & 31;

    float4 v = *reinterpret_cast<const float4*>(&attn[base + t * 4]);

    float m = fmaxf(fmaxf(v.x, v.y), fmaxf(v.z, v.w));
#pragma unroll
    for (int o = 16; o; o >>= 1) m = fmaxf(m, __shfl_xor_sync(0xffffffffu, m, o));
    if (lane == 0) s1[w] = m;
    __syncthreads();
    float M = s1[0];
#pragma unroll
    for (int i = 1; i < 8; i++) M = fmaxf(M, s1[i]);

    float4 p;
    p.x = __expf(v.x - M); p.y = __expf(v.y - M);
    p.z = __expf(v.z - M); p.w = __expf(v.w - M);
    float s = (p.x + p.y) + (p.z + p.w);
#pragma unroll
    for (int o = 16; o; o >>= 1) s += __shfl_xor_sync(0xffffffffu, s, o);
    if (lane == 0) s2[w] = s;
    __syncthreads();
    float S = s2[0];
#pragma unroll
    for (int i = 1; i < 8; i++) S += s2[i];
    float inv = 1.0f / S;

    p.x *= inv; p.y *= inv; p.z *= inv; p.w *= inv;
    *reinterpret_cast<float4*>(&attn[base + t * 4]) = p;
}

// ---------------------------------------------------------------------------
// Kernel 3: p_val = p_attn @ V. Double-buffered; B=V transposed via k-pairs.
// ---------------------------------------------------------------------------
__global__ __launch_bounds__(256, 2) void pv_kernel(
    const float* __restrict__ P,
    const float* __restrict__ V,
    float* __restrict__ out)
{
    extern __shared__ float smem[];

    const int b     = blockIdx.z;
    const int qBase = blockIdx.y * 128;
    const int nBase = blockIdx.x * 128;

    const float* Pb = P + (size_t)b * N_ * N_;
    const float* Vb = V + (size_t)b * N_ * C_;

    const int tid  = threadIdx.x;
    const int lane = tid & 31;
    const int w    = tid >> 5;
    const int wm   = w >> 2;
    const int wn   = w & 3;
    const int g    = lane >> 2;
    const int cq   = lane & 3;

    const int lrow[2] = { (tid        ) >> 2, (tid + 256) >> 2 };
    const int lc4     = (tid & 3) * 4;
    const int nIdx    = tid & 127;     // B loader: column of V
    const int half    = tid >> 7;      // k-halves {0..7} vs {8..15}

    float acc[4][4][4];
#pragma unroll
    for (int i = 0; i < 4; i++)
#pragma unroll
        for (int j = 0; j < 4; j++)
#pragma unroll
            for (int r = 0; r < 4; r++) acc[i][j][r] = 0.0f;

    float4 vp[2];
    float  vv0[4], vv1[4];

    auto load_chunk = [&](int k0) {
#pragma unroll
        for (int e = 0; e < 2; e++)
            vp[e] = *reinterpret_cast<const float4*>(
                &Pb[(size_t)(qBase + lrow[e]) * N_ + k0 + lc4]);
#pragma unroll
        for (int kb = 0; kb < 4; kb++) {
            int k = half * 8 + kb;
            vv0[kb] = Vb[(size_t)(k0 + k) * C_ + nBase + nIdx];
            vv1[kb] = Vb[(size_t)(k0 + k + 4) * C_ + nBase + nIdx];
        }
    };

    auto store_chunk = [&](float* nb) {
        float* Ah = nb;            float* Al = nb + TILE;
        float* Bh = nb + 2 * TILE; float* Bl = nb + 3 * TILE;
#pragma unroll
        for (int e = 0; e < 2; e++)
            store_split4(Ah, Al, lrow[e], lc4, vp[e]);
#pragma unroll
        for (int kb = 0; kb < 4; kb++) {
            float h0, l0, h1, l1;
            split_tf32(vv0[kb], h0, l0);
            split_tf32(vv1[kb], h1, l1);
            int off = nIdx * STR + half * 8 + 2 * kb;   // p(k), p(k+4) adjacent
            *reinterpret_cast<float2*>(&Bh[off]) = make_float2(h0, h1);
            *reinterpret_cast<float2*>(&Bl[off]) = make_float2(l0, l1);
        }
    };

    load_chunk(0);
    store_chunk(smem);
    __syncthreads();

    int buf = 0;
    for (int k0 = 0; k0 < N_; k0 += KC, buf ^= 1) {
        const bool more = (k0 + KC) < N_;
        if (more) load_chunk(k0 + KC);
        const float* base = smem + buf * 4 * TILE;
        compute_chunk(base, base + TILE, base + 2 * TILE, base + 3 * TILE,
                      acc, wm, wn, g, cq);
        if (more) store_chunk(smem + (buf ^ 1) * 4 * TILE);
        __syncthreads();
    }

#pragma unroll
    for (int i = 0; i < 4; i++) {
        int r0 = qBase + wm * 64 + i * 16 + g;
        int r1 = r0 + 8;
#pragma unroll
        for (int j = 0; j < 4; j++) {
            int col = nBase + wn * 32 + j * 8 + 2 * cq;
            size_t i0 = ((size_t)b * N_ + r0) * C_ + col;
            size_t i1 = ((size_t)b * N_ + r1) * C_ + col;
            *reinterpret_cast<float2*>(&out[i0]) = make_float2(acc[i][j][0], acc[i][j][1]);
            *reinterpret_cast<float2*>(&out[i1]) = make_float2(acc[i][j][2], acc[i][j][3]);
        }
    }
}

// ---------------------------------------------------------------------------
// Launch
// ---------------------------------------------------------------------------
extern "C" void kernel_launch(void* const* d_in, const int* in_sizes, int n_in,
                              void* d_out, int out_size)
{
    const float* Q    = (const float*)d_in[0];
    const float* K    = (const float*)d_in[1];
    const float* V    = (const float*)d_in[2];
    const int*   mask = (const int*)d_in[3];
    const float* dis  = (const float*)d_in[4];

    float* out    = (float*)d_out;
    float* p_val  = out;                          // [B, N, C]
    float* p_attn = out + (size_t)B_ * N_ * C_;   // [B, N, N]

    const int smemBytes = 2 * 4 * TILE * sizeof(float);   // 81920
    cudaFuncSetAttribute(qk_scores_kernel,
                         cudaFuncAttributeMaxDynamicSharedMemorySize, smemBytes);
    cudaFuncSetAttribute(pv_kernel,
                         cudaFuncAttributeMaxDynamicSharedMemorySize, smemBytes);

    qk_scores_kernel<<<dim3(N_ / 128, N_ / 128, B_), 256, smemBytes>>>(Q, K, dis, mask, p_attn);
    softmax_kernel<<<B_ * N_, 256>>>(p_attn);
    pv_kernel<<<dim3(C_ / 128, N_ / 128, B_), 256, smemBytes>>>(p_attn, V, p_val);
}